// round 1
// baseline (speedup 1.0000x reference)
#include <cuda_runtime.h>
#include <cstdint>

typedef unsigned long long u64;

#define NPRED      25200
#define NCH        85
#define NBATCH     16
#define TOPK       2048
#define MAXDET     300
#define NCHUNK     13          // ceil(25200/2048)
#define CONF       0.25f
#define NMS_T      0.45f

// scratch: sorted chunk keys per (batch, chunk)
__device__ u64 g_chunks[NBATCH * NCHUNK * TOPK];

__device__ __forceinline__ unsigned f2sortable(float f) {
    unsigned v = __float_as_uint(f);
    return (v & 0x80000000u) ? ~v : (v | 0x80000000u);
}
__device__ __forceinline__ float sortable2f(unsigned s) {
    unsigned v = (s & 0x80000000u) ? (s & 0x7FFFFFFFu) : ~s;
    return __uint_as_float(v);
}

// ---------------------------------------------------------------------------
// K1: per (chunk, batch) — build 64-bit keys and bitonic-sort 2048 descending
// ---------------------------------------------------------------------------
__global__ __launch_bounds__(1024, 1)
void yolo_sort_chunks(const float* __restrict__ preds) {
    __shared__ u64 s[TOPK];
    const int c = blockIdx.x, b = blockIdx.y, tid = threadIdx.x;

    #pragma unroll
    for (int r = tid; r < TOPK; r += 1024) {
        int idx = c * TOPK + r;
        u64 key = 0ULL;
        if (idx < NPRED) {
            float sv = preds[((size_t)b * NPRED + idx) * NCH + 4];
            float m = (sv > CONF) ? sv : -1.0f;
            key = ((u64)f2sortable(m) << 32) | (unsigned)(~(unsigned)idx);
        }
        s[r] = key;
    }

    for (unsigned k = 2; k <= TOPK; k <<= 1) {
        for (unsigned j = k >> 1; j > 0; j >>= 1) {
            __syncthreads();
            unsigned i = 2u * tid - (tid & (j - 1));
            unsigned l = i + j;
            u64 a = s[i], e = s[l];
            bool dir = ((i & k) == 0);      // descending blocks
            if ((a < e) == dir) { s[i] = e; s[l] = a; }
        }
    }
    __syncthreads();

    u64* dst = g_chunks + ((size_t)b * NCHUNK + c) * TOPK;
    dst[tid]        = s[tid];
    dst[tid + 1024] = s[tid + 1024];
}

// ---------------------------------------------------------------------------
// K2: per batch — fold chunks to top-2048 (sorted), decode boxes, greedy NMS
//     with early exit at 300 kept, emit (box, score, label)
// ---------------------------------------------------------------------------
__global__ __launch_bounds__(1024, 1)
void yolo_finalize(const float* __restrict__ preds,
                   const int* __restrict__ image_sizes,
                   float* __restrict__ out) {
    extern __shared__ unsigned char sm_raw[];
    u64*   keyA = (u64*)sm_raw;                 // 2048
    u64*   keyB = keyA + TOPK;                  // 2048
    float* bx0  = (float*)(keyB + TOPK);        // 2048 each:
    float* by0  = bx0 + TOPK;
    float* bx1  = by0 + TOPK;
    float* by1  = bx1 + TOPK;
    float* sc   = by1 + TOPK;
    float* area = sc + TOPK;
    int*   orig = (int*)(area + TOPK);          // 2048
    int*   keptIdx = orig + TOPK;               // 304
    unsigned char* removed = (unsigned char*)(keptIdx + 304); // 2048

    const int b = blockIdx.x, tid = threadIdx.x;

    // ---- fold sorted chunks into keyA (top-2048 descending) ----
    {
        const u64* src = g_chunks + (size_t)b * NCHUNK * TOPK;
        keyA[tid]        = src[tid];
        keyA[tid + 1024] = src[tid + 1024];
        for (int c = 1; c < NCHUNK; ++c) {
            const u64* sc_ = src + (size_t)c * TOPK;
            keyB[tid]        = sc_[tid];
            keyB[tid + 1024] = sc_[tid + 1024];
            __syncthreads();
            #pragma unroll
            for (int r = tid; r < TOPK; r += 1024) {
                u64 o = keyB[(TOPK - 1) - r];
                if (o > keyA[r]) keyA[r] = o;   // bitonic result holds top-2048
            }
            for (int j = 1024; j > 0; j >>= 1) {  // descending bitonic merge
                __syncthreads();
                int i = 2 * tid - (tid & (j - 1));
                int l = i + j;
                u64 a = keyA[i], e = keyA[l];
                if (a < e) { keyA[i] = e; keyA[l] = a; }
            }
            __syncthreads();
        }
    }
    __syncthreads();

    // ---- decode boxes (exact fp32 op sequence, no FMA contraction) ----
    const float H  = (float)image_sizes[b * 2 + 0];
    const float W  = (float)image_sizes[b * 2 + 1];
    const float rh = __fdiv_rn(H, 640.0f);
    const float rw = __fdiv_rn(W, 640.0f);

    #pragma unroll
    for (int r = tid; r < TOPK; r += 1024) {
        u64 key = keyA[r];
        unsigned o = ~((unsigned)key);
        float s = sortable2f((unsigned)(key >> 32));
        const float* p = preds + ((size_t)b * NPRED + o) * NCH;
        float x = p[0], y = p[1], w = p[2], h = p[3];
        float xm = __fsub_rn(x, __fmul_rn(w, 0.5f));
        float ym = __fsub_rn(y, __fmul_rn(h, 0.5f));
        float xM = __fadd_rn(xm, w);
        float yM = __fadd_rn(ym, h);
        float c0 = fminf(fmaxf(__fmul_rn(xm, rw), 0.0f), W);
        float c1 = fminf(fmaxf(__fmul_rn(ym, rh), 0.0f), H);
        float c2 = fminf(fmaxf(__fmul_rn(xM, rw), 0.0f), W);
        float c3 = fminf(fmaxf(__fmul_rn(yM, rh), 0.0f), H);
        bx0[r] = c0; by0[r] = c1; bx1[r] = c2; by1[r] = c3;
        sc[r] = s; orig[r] = (int)o;
        area[r] = __fmul_rn(fmaxf(__fsub_rn(c2, c0), 0.0f),
                            fmaxf(__fsub_rn(c3, c1), 0.0f));
        removed[r] = 0;
    }
    __syncthreads();

    // ---- greedy NMS (sequential in score order), early exit at 300 kept ----
    int kept = 0;
    for (int i = 0; i < TOPK; ++i) {
        if (removed[i] || !(sc[i] > CONF)) continue;   // uniform across block
        if (tid == 0) keptIdx[kept] = i;
        kept++;
        if (kept >= MAXDET) break;                     // later boxes irrelevant
        float ax0 = bx0[i], ay0 = by0[i], ax1 = bx1[i], ay1 = by1[i], aa = area[i];
        for (int j = i + 1 + tid; j < TOPK; j += 1024) {
            float ltx = fmaxf(ax0, bx0[j]);
            float lty = fmaxf(ay0, by0[j]);
            float rbx = fminf(ax1, bx1[j]);
            float rby = fminf(ay1, by1[j]);
            float iw  = fmaxf(__fsub_rn(rbx, ltx), 0.0f);
            float ih  = fmaxf(__fsub_rn(rby, lty), 0.0f);
            float inter = __fmul_rn(iw, ih);
            float uni   = __fsub_rn(__fadd_rn(area[j], aa), inter);
            float iou   = __fdiv_rn(inter, __fadd_rn(uni, 1e-7f));
            if (iou > NMS_T) removed[j] = 1;
        }
        __syncthreads();
    }
    __syncthreads();

    // ---- emit top-300 detections; argmax label only for kept rows ----
    for (int r = tid; r < MAXDET; r += 1024) {
        float o0 = 0.f, o1 = 0.f, o2 = 0.f, o3 = 0.f, o4 = 0.f, o5 = 0.f;
        if (r < kept) {
            int i = keptIdx[r];
            o0 = bx0[i]; o1 = by0[i]; o2 = bx1[i]; o3 = by1[i]; o4 = sc[i];
            const float* p = preds + ((size_t)b * NPRED + orig[i]) * NCH + 5;
            float best = p[0]; int bi = 0;
            #pragma unroll 4
            for (int c = 1; c < 80; ++c) {
                float v = p[c];
                if (v > best) { best = v; bi = c; }   // first-max == jnp.argmax
            }
            o5 = (float)(bi + 1);
        }
        float* po = out + ((size_t)b * MAXDET + r) * 6;
        po[0] = o0; po[1] = o1; po[2] = o2; po[3] = o3; po[4] = o4; po[5] = o5;
    }
}

// ---------------------------------------------------------------------------
extern "C" void kernel_launch(void* const* d_in, const int* in_sizes, int n_in,
                              void* d_out, int out_size) {
    const float* preds = (const float*)d_in[0];
    const int*   iszs  = (const int*)d_in[1];
    float*       out   = (float*)d_out;

    const int smem2 = 2 * TOPK * 8       // keyA, keyB
                    + 6 * TOPK * 4       // bx0,by0,bx1,by1,sc,area
                    + TOPK * 4           // orig
                    + 304 * 4            // keptIdx
                    + TOPK;              // removed
    cudaFuncSetAttribute(yolo_finalize,
                         cudaFuncAttributeMaxDynamicSharedMemorySize, smem2);

    yolo_sort_chunks<<<dim3(NCHUNK, NBATCH), 1024>>>(preds);
    yolo_finalize<<<NBATCH, 1024, smem2>>>(preds, iszs, out);
}

// round 5
// speedup vs baseline: 1.7770x; 1.7770x over previous
#include <cuda_runtime.h>
#include <cstdint>

typedef unsigned long long u64;
typedef unsigned int u32;

#define NPRED   25200
#define NCH     85
#define NBATCH  16
#define TOPK    2048
#define MAXDET  300
#define NCHUNK  13
#define CONF    0.25f
#define NMS_T   0.45f
#define WSZ     256         // NMS window size
#define WW      8           // u32 words per window row (WSZ/32)

__device__ u64    g_chunks[NBATCH * NCHUNK * TOPK];
__device__ float4 g_box  [NBATCH * TOPK];
__device__ float  g_area [NBATCH * TOPK];
__device__ float  g_score[NBATCH * TOPK];
__device__ int    g_orig [NBATCH * TOPK];
__device__ int    g_nvalid[NBATCH];

__device__ __forceinline__ unsigned f2sortable(float f) {
    unsigned v = __float_as_uint(f);
    return (v & 0x80000000u) ? ~v : (v | 0x80000000u);
}
__device__ __forceinline__ float sortable2f(unsigned s) {
    unsigned v = (s & 0x80000000u) ? (s & 0x7FFFFFFFu) : ~s;
    return __uint_as_float(v);
}

// Bitwise-identical to (inter/(union+1e-7)) > 0.45: multiply-compare bracket,
// exact division only inside the ±4e-6 ambiguity band (div err ~6e-8).
__device__ __forceinline__ bool sup_test(float4 a, float aa, float4 bb, float ab) {
    float ltx = fmaxf(a.x, bb.x);
    float lty = fmaxf(a.y, bb.y);
    float rbx = fminf(a.z, bb.z);
    float rby = fminf(a.w, bb.w);
    float iw  = fmaxf(__fsub_rn(rbx, ltx), 0.0f);
    float ih  = fmaxf(__fsub_rn(rby, lty), 0.0f);
    float inter = __fmul_rn(iw, ih);
    float uni   = __fsub_rn(__fadd_rn(ab, aa), inter);
    float u     = __fadd_rn(uni, 1e-7f);
    if (inter > __fmul_rn(u, 0.45000180f)) return true;
    if (inter < __fmul_rn(u, 0.44999820f)) return false;
    return __fdiv_rn(inter, u) > NMS_T;
}

// ---------------------------------------------------------------------------
// K1: per (chunk, batch) — 64-bit keys, bitonic sort 2048 descending
//     key = (sortable(masked_score) << 32) | ~index  => lax.top_k tie order
// ---------------------------------------------------------------------------
__global__ __launch_bounds__(1024, 1)
void yolo_sort_chunks(const float* __restrict__ preds) {
    __shared__ u64 s[TOPK];
    const int c = blockIdx.x, b = blockIdx.y, tid = threadIdx.x;

    #pragma unroll
    for (int r = tid; r < TOPK; r += 1024) {
        int idx = c * TOPK + r;
        u64 key = 0ULL;
        if (idx < NPRED) {
            float sv = preds[((size_t)b * NPRED + idx) * NCH + 4];
            float m = (sv > CONF) ? sv : -1.0f;
            key = ((u64)f2sortable(m) << 32) | (unsigned)(~(unsigned)idx);
        }
        s[r] = key;
    }
    for (unsigned k = 2; k <= TOPK; k <<= 1) {
        for (unsigned j = k >> 1; j > 0; j >>= 1) {
            __syncthreads();
            unsigned i = 2u * tid - (tid & (j - 1));
            unsigned l = i + j;
            u64 a = s[i], e = s[l];
            bool dir = ((i & k) == 0);
            if ((a < e) == dir) { s[i] = e; s[l] = a; }
        }
    }
    __syncthreads();
    u64* dst = g_chunks + ((size_t)b * NCHUNK + c) * TOPK;
    dst[tid]        = s[tid];
    dst[tid + 1024] = s[tid + 1024];
}

// ---------------------------------------------------------------------------
// K2: per batch — fold 13 sorted chunks to top-2048 (max-merge + 11-stage
//     bitonic re-merge), then decode/clip boxes -> SoA scratch
// ---------------------------------------------------------------------------
__global__ __launch_bounds__(1024, 1)
void yolo_merge_decode(const float* __restrict__ preds,
                       const int* __restrict__ image_sizes) {
    __shared__ u64 keyA[TOPK];
    __shared__ u64 keyB[TOPK];
    const int b = blockIdx.x, tid = threadIdx.x;

    const u64* src = g_chunks + (size_t)b * NCHUNK * TOPK;
    keyA[tid]        = src[tid];
    keyA[tid + 1024] = src[tid + 1024];
    for (int c = 1; c < NCHUNK; ++c) {
        const u64* sc_ = src + (size_t)c * TOPK;
        keyB[tid]        = sc_[tid];
        keyB[tid + 1024] = sc_[tid + 1024];
        __syncthreads();
        #pragma unroll
        for (int r = tid; r < TOPK; r += 1024) {
            u64 o = keyB[(TOPK - 1) - r];
            if (o > keyA[r]) keyA[r] = o;
        }
        for (int j = 1024; j > 0; j >>= 1) {
            __syncthreads();
            int i = 2 * tid - (tid & (j - 1));
            int l = i + j;
            u64 a = keyA[i], e = keyA[l];
            if (a < e) { keyA[i] = e; keyA[l] = a; }
        }
        __syncthreads();
    }
    __syncthreads();

    const float H  = (float)image_sizes[b * 2 + 0];
    const float W  = (float)image_sizes[b * 2 + 1];
    const float rh = __fdiv_rn(H, 640.0f);
    const float rw = __fdiv_rn(W, 640.0f);

    #pragma unroll
    for (int r = tid; r < TOPK; r += 1024) {
        u64 key = keyA[r];
        unsigned o = ~((unsigned)key);
        float s = sortable2f((unsigned)(key >> 32));
        const float* p = preds + ((size_t)b * NPRED + o) * NCH;
        float x = p[0], y = p[1], w = p[2], h = p[3];
        float xm = __fsub_rn(x, __fmul_rn(w, 0.5f));
        float ym = __fsub_rn(y, __fmul_rn(h, 0.5f));
        float xM = __fadd_rn(xm, w);
        float yM = __fadd_rn(ym, h);
        float c0 = fminf(fmaxf(__fmul_rn(xm, rw), 0.0f), W);
        float c1 = fminf(fmaxf(__fmul_rn(ym, rh), 0.0f), H);
        float c2 = fminf(fmaxf(__fmul_rn(xM, rw), 0.0f), W);
        float c3 = fminf(fmaxf(__fmul_rn(yM, rh), 0.0f), H);
        int gi = b * TOPK + r;
        g_box[gi]   = make_float4(c0, c1, c2, c3);
        g_area[gi]  = __fmul_rn(fmaxf(__fsub_rn(c2, c0), 0.0f),
                                fmaxf(__fsub_rn(c3, c1), 0.0f));
        g_score[gi] = s;
        g_orig[gi]  = (int)o;

        bool v0 = (s > CONF);
        bool v1 = false;
        if (r < TOPK - 1) {
            float s1 = sortable2f((unsigned)(keyA[r + 1] >> 32));
            v1 = (s1 > CONF);
        }
        if (v0 && !v1) g_nvalid[b] = r + 1;
        if (r == 0 && !v0) g_nvalid[b] = 0;
    }
}

// ---------------------------------------------------------------------------
// K3: fused windowed NMS + emit. One block (1024 thr) per batch.
//   Per 256-candidate window:
//     A) cross: window candidates vs kept pivots (4 thr/candidate)
//     B) intra: 256x256/2 bitmatrix (4 thr/row, 2 words each)
//     C) scan: warp 0, alive bits in registers, AND out kept rows
//   Lazy evaluation: only kept pivots' suppression ever computed vs later
//   windows -> ~570K tests/batch instead of 2.1M (full matrix).
// ---------------------------------------------------------------------------
// dynamic smem layout (bytes):
#define SM_BOX    0                       // float4[2048]  32768
#define SM_AREA   32768                   // float [2048]   8192
#define SM_KBOX   40960                   // float4[300]    4800
#define SM_KAREA  45760                   // float [300]    1200
#define SM_KIDX   46960                   // int   [300]    1200
#define SM_MAT    48160                   // u32 [256*8]    8192
#define SM_SUP    56352                   // u32 [256]      1024
#define SM_KEPT   57376                   // int            4
#define SM_TOTAL  57408

__global__ __launch_bounds__(1024, 1)
void yolo_nms_emit(const float* __restrict__ preds,
                   float* __restrict__ out) {
    extern __shared__ unsigned char sm[];
    float4* sbox  = (float4*)(sm + SM_BOX);
    float*  sarea = (float*) (sm + SM_AREA);
    float4* kbox  = (float4*)(sm + SM_KBOX);
    float*  karea = (float*) (sm + SM_KAREA);
    int*    kidx  = (int*)   (sm + SM_KIDX);
    u32*    mat   = (u32*)   (sm + SM_MAT);
    u32*    ssup  = (u32*)   (sm + SM_SUP);
    int*    skept = (int*)   (sm + SM_KEPT);

    const int b = blockIdx.x, tid = threadIdx.x;
    const int nv = g_nvalid[b];

    for (int r = tid; r < TOPK; r += 1024) {
        sbox[r]  = g_box[b * TOPK + r];
        sarea[r] = g_area[b * TOPK + r];
    }
    if (tid == 0) *skept = 0;

    for (int wbase = 0; wbase < nv; wbase += WSZ) {
        __syncthreads();                       // prev scan done / init done
        const int kept = *skept;
        if (kept >= MAXDET) break;             // uniform
        const int wn = (nv - wbase < WSZ) ? (nv - wbase) : WSZ;
        if (tid < WSZ) ssup[tid] = 0;
        __syncthreads();

        // ---- phase A: candidates vs kept pivots (4 threads / candidate) ----
        {
            const int c = tid >> 2, q = tid & 3;
            if (c < wn && kept > 0) {
                float4 a = sbox[wbase + c];
                float aa = sarea[wbase + c];
                bool hit = false;
                for (int p = q; p < kept; p += 4)
                    if (sup_test(kbox[p], karea[p], a, aa)) { hit = true; break; }
                if (hit) atomicOr(&ssup[c], 1u);
            }
        }
        // ---- phase B: intra-window bitmatrix (4 threads / row, 2 words) ----
        {
            const int r = tid >> 2;
            if (r < wn) {
                float4 a = sbox[wbase + r];
                float aa = sarea[wbase + r];
                #pragma unroll
                for (int h = 0; h < 2; ++h) {
                    const int w  = (tid & 3) * 2 + h;
                    const int j0 = w * 32;
                    u32 bits = 0;
                    if (j0 + 31 > r) {
                        #pragma unroll 8
                        for (int k = 0; k < 32; ++k) {
                            int j = j0 + k;
                            if (j > r && j < wn &&
                                sup_test(a, aa, sbox[wbase + j], sarea[wbase + j]))
                                bits |= (1u << k);
                        }
                    }
                    mat[r * WW + w] = bits;
                }
            }
        }
        __syncthreads();

        // ---- phase C: greedy scan (warp 0, alive masks in registers) ----
        if (tid < 32) {
            const int lane = tid;
            u32 alive = 0;
            #pragma unroll
            for (int w = 0; w < WW; ++w) {
                int c = w * 32 + lane;
                u32 wd = __ballot_sync(0xFFFFFFFFu, (c < wn) && (ssup[c] == 0));
                if (lane == w) alive = wd;
            }
            int k2 = kept;
            while (k2 < MAXDET) {
                u32 bal = __ballot_sync(0xFFFFFFFFu, alive != 0);
                if (!bal) break;
                int l = __ffs(bal) - 1;
                int bit = __ffs(alive) - 1;
                bit = __shfl_sync(0xFFFFFFFFu, bit, l);
                int c = l * 32 + bit;
                if (lane == 0) {
                    kidx[k2]  = wbase + c;
                    kbox[k2]  = sbox[wbase + c];
                    karea[k2] = sarea[wbase + c];
                }
                k2++;
                if (k2 >= MAXDET) break;
                u32 rw = (lane < WW) ? mat[c * WW + lane] : 0u;
                if (lane == l) alive &= ~(1u << bit);
                alive &= ~rw;
            }
            if (lane == 0) *skept = k2;
        }
    }
    __syncthreads();
    const int kept = *skept;

    // ---- emit top-300; per-detection 80-class argmax (first max) ----
    for (int r = tid; r < MAXDET; r += 1024) {
        float o0 = 0.f, o1 = 0.f, o2 = 0.f, o3 = 0.f, o4 = 0.f, o5 = 0.f;
        if (r < kept) {
            int i = kidx[r];
            float4 bx = sbox[i];
            o0 = bx.x; o1 = bx.y; o2 = bx.z; o3 = bx.w;
            o4 = g_score[b * TOPK + i];
            const float* p = preds + ((size_t)b * NPRED + g_orig[b * TOPK + i]) * NCH + 5;
            float best = p[0]; int bi = 0;
            #pragma unroll 8
            for (int c = 1; c < 80; ++c) {
                float v = p[c];
                if (v > best) { best = v; bi = c; }
            }
            o5 = (float)(bi + 1);
        }
        float* po = out + ((size_t)b * MAXDET + r) * 6;
        po[0] = o0; po[1] = o1; po[2] = o2;
        po[3] = o3; po[4] = o4; po[5] = o5;
    }
}

// ---------------------------------------------------------------------------
extern "C" void kernel_launch(void* const* d_in, const int* in_sizes, int n_in,
                              void* d_out, int out_size) {
    const float* preds = (const float*)d_in[0];
    const int*   iszs  = (const int*)d_in[1];
    float*       out   = (float*)d_out;

    cudaFuncSetAttribute(yolo_nms_emit,
                         cudaFuncAttributeMaxDynamicSharedMemorySize, SM_TOTAL);

    yolo_sort_chunks<<<dim3(NCHUNK, NBATCH), 1024>>>(preds);
    yolo_merge_decode<<<NBATCH, 1024>>>(preds, iszs);
    yolo_nms_emit<<<NBATCH, 1024, SM_TOTAL>>>(preds, out);
}